// round 5
// baseline (speedup 1.0000x reference)
#include <cuda_runtime.h>
#include <math.h>

#define BB   128
#define SS   1024
#define TT   (BB*SS)          // 131072 tokens
#define IND  192
#define DD   64
#define EE   4
#define HID  256
#define NCLS 10

#define PH2 66   // activation tile pitch in float2
#define PW2 66   // weight tile pitch in float2

// ------------------------- scratch (device globals) ------------------------
__device__ float g_h1[(size_t)TT * DD];      // h1; later reused as moe output
__device__ float g_h [(size_t)TT * DD];      // h = h1@W2+b2
__device__ float g_gate[TT];
__device__ int   g_idx[(size_t)EE * TT];
__device__ int   g_cnt[EE];
__device__ float g_psum[EE];
__device__ float g_z[BB * DD];

__device__ __forceinline__ float gelu_f(float v) {
    return 0.5f * v * (1.0f + erff(v * 0.70710678118654752440f));
}
// split fp32 into tf32 hi + tf32 lo
__device__ __forceinline__ float2 split_tf(float f) {
    unsigned hu, lu;
    asm("cvt.rna.tf32.f32 %0, %1;" : "=r"(hu) : "f"(f));
    float hi = __uint_as_float(hu);
    asm("cvt.rna.tf32.f32 %0, %1;" : "=r"(lu) : "f"(f - hi));
    return make_float2(hi, __uint_as_float(lu));
}
__device__ __forceinline__ void mma8(float* c, const unsigned* a, unsigned b0, unsigned b1) {
    asm volatile(
        "mma.sync.aligned.m16n8k8.row.col.f32.tf32.tf32.f32 "
        "{%0,%1,%2,%3},{%4,%5,%6,%7},{%8,%9},{%0,%1,%2,%3};"
        : "+f"(c[0]), "+f"(c[1]), "+f"(c[2]), "+f"(c[3])
        : "r"(a[0]), "r"(a[1]), "r"(a[2]), "r"(a[3]), "r"(b0), "r"(b1));
}
// tf32x3: acc += al*bh + ah*bl + ah*bh
__device__ __forceinline__ void mma3(float* c, const unsigned* ah, const unsigned* al,
                                     unsigned bh0, unsigned bh1, unsigned bl0, unsigned bl1) {
    mma8(c, al, bh0, bh1);
    mma8(c, ah, bl0, bl1);
    mma8(c, ah, bh0, bh1);
}
__device__ __forceinline__ void ldA2(unsigned* ah, unsigned* al,
                                     const float2* base, int pitch, int g, int tg) {
    float2 v0 = base[g * pitch + tg];
    float2 v1 = base[(g + 8) * pitch + tg];
    float2 v2 = base[g * pitch + tg + 4];
    float2 v3 = base[(g + 8) * pitch + tg + 4];
    ah[0] = __float_as_uint(v0.x); al[0] = __float_as_uint(v0.y);
    ah[1] = __float_as_uint(v1.x); al[1] = __float_as_uint(v1.y);
    ah[2] = __float_as_uint(v2.x); al[2] = __float_as_uint(v2.y);
    ah[3] = __float_as_uint(v3.x); al[3] = __float_as_uint(v3.y);
}
// one warp's m32 x n32 x k64 tf32x3 GEMM over pitched float2 tiles
__device__ __forceinline__ void gemm_m32n32(float acc[2][4][4],
                                            const float2* A, const float2* W,
                                            int row0, int nb, int g, int tg) {
#pragma unroll
    for (int ks = 0; ks < 64; ks += 8) {
        unsigned ah0[4], al0[4], ah1[4], al1[4];
        ldA2(ah0, al0, A + row0 * PH2 + ks, PH2, g, tg);
        ldA2(ah1, al1, A + (row0 + 16) * PH2 + ks, PH2, g, tg);
#pragma unroll
        for (int j = 0; j < 4; ++j) {
            float2 wb0 = W[(ks + tg) * PW2 + nb + j * 8 + g];
            float2 wb1 = W[(ks + tg + 4) * PW2 + nb + j * 8 + g];
            unsigned bh0 = __float_as_uint(wb0.x), bh1 = __float_as_uint(wb1.x);
            unsigned bl0 = __float_as_uint(wb0.y), bl1 = __float_as_uint(wb1.y);
            mma3(acc[0][j], ah0, al0, bh0, bh1, bl0, bl1);
            mma3(acc[1][j], ah1, al1, bh0, bh1, bl0, bl1);
        }
    }
}

// ------------------------- k0: zero counters -------------------------------
__global__ void k0_zero() {
    int t = threadIdx.x;
    if (t < EE) { g_cnt[t] = 0; g_psum[t] = 0.0f; }
}

// ------------------------- k1: h1 = gelu(x @ W1 + b1) ----------------------
// 128 tokens x 64 outs, 8 warps as 4(m) x 2(n), warp tile m32 x n32, K=3x64
extern __shared__ float2 sm1[];
__global__ void __launch_bounds__(256) k1_pe1(const float* __restrict__ x,
                                              const float* __restrict__ w1,
                                              const float* __restrict__ b1) {
    float2* xs = sm1;                 // [128][64] pitched PH2
    float2* ws = sm1 + 128 * PH2;     // [64][64]  pitched PW2

    const int t = threadIdx.x, lane = t & 31, w = t >> 5;
    const int g = lane >> 2, tg = lane & 3;
    const int row0 = (w & 3) * 32, nb = (w >> 2) * 32;
    const int tok0 = blockIdx.x * 128;

    float acc[2][4][4];
#pragma unroll
    for (int mt = 0; mt < 2; ++mt)
#pragma unroll
        for (int j = 0; j < 4; ++j)
#pragma unroll
            for (int c = 0; c < 4; ++c) acc[mt][j][c] = 0.0f;

    for (int it = 0; it < 3; ++it) {
        if (it) __syncthreads();
        {   // stage x chunk [128][64]
            int row = t >> 1, cb = (t & 1) * 32;
            const float* src = x + (size_t)(tok0 + row) * IND + it * 64 + cb;
            float2* dst = xs + row * PH2 + cb;
#pragma unroll
            for (int q = 0; q < 8; ++q) {
                float4 v = *(const float4*)(src + q * 4);
                dst[q * 4 + 0] = split_tf(v.x);
                dst[q * 4 + 1] = split_tf(v.y);
                dst[q * 4 + 2] = split_tf(v.z);
                dst[q * 4 + 3] = split_tf(v.w);
            }
        }
#pragma unroll
        for (int p = 0; p < 16; ++p) {   // stage w1 chunk [64][64]
            int idx = p * 256 + t;
            int kk = idx >> 6, nn = idx & 63;
            ws[kk * PW2 + nn] = split_tf(w1[(size_t)(it * 64 + kk) * DD + nn]);
        }
        __syncthreads();
        gemm_m32n32(acc, xs, ws, row0, nb, g, tg);
    }

#pragma unroll
    for (int mt = 0; mt < 2; ++mt)
#pragma unroll
        for (int j = 0; j < 4; ++j) {
            int n0 = nb + j * 8 + 2 * tg;
            float bx = __ldg(&b1[n0]), by = __ldg(&b1[n0 + 1]);
            int r = tok0 + row0 + mt * 16 + g;
            float2 v0, v1;
            v0.x = gelu_f(acc[mt][j][0] + bx); v0.y = gelu_f(acc[mt][j][1] + by);
            v1.x = gelu_f(acc[mt][j][2] + bx); v1.y = gelu_f(acc[mt][j][3] + by);
            *(float2*)&g_h1[(size_t)r * DD + n0]       = v0;
            *(float2*)&g_h1[(size_t)(r + 8) * DD + n0] = v1;
        }
}

// ------------------- k2: h = h1 @ W2 + b2, fused gate ----------------------
extern __shared__ float2 sm2[];
__global__ void __launch_bounds__(256) k2_pe2_gate(const float* __restrict__ w2,
                                                   const float* __restrict__ b2,
                                                   const float* __restrict__ gw,
                                                   const float* __restrict__ gb) {
    float2* hs = sm2;
    float2* ws = sm2 + 128 * PH2;
    float*  hsf = (float*)sm2;        // alias after GEMM: [128][65] fp32
    __shared__ float gws[DD * EE];
    __shared__ float sps[EE];

    const int t = threadIdx.x, lane = t & 31, w = t >> 5;
    const int g = lane >> 2, tg = lane & 3;
    const int row0 = (w & 3) * 32, nb = (w >> 2) * 32;
    const int tok0 = blockIdx.x * 128;

    gws[t] = gw[t];                   // 256 == DD*EE
    if (t < EE) sps[t] = 0.0f;

    {   // stage h1 tile [128][64]
        int row = t >> 1, cb = (t & 1) * 32;
        const float* src = g_h1 + (size_t)(tok0 + row) * DD + cb;
        float2* dst = hs + row * PH2 + cb;
#pragma unroll
        for (int q = 0; q < 8; ++q) {
            float4 v = *(const float4*)(src + q * 4);
            dst[q * 4 + 0] = split_tf(v.x);
            dst[q * 4 + 1] = split_tf(v.y);
            dst[q * 4 + 2] = split_tf(v.z);
            dst[q * 4 + 3] = split_tf(v.w);
        }
    }
#pragma unroll
    for (int p = 0; p < 16; ++p) {   // stage w2 [64][64]
        int idx = p * 256 + t;
        int kk = idx >> 6, nn = idx & 63;
        ws[kk * PW2 + nn] = split_tf(w2[(size_t)kk * DD + nn]);
    }
    __syncthreads();

    float acc[2][4][4];
#pragma unroll
    for (int mt = 0; mt < 2; ++mt)
#pragma unroll
        for (int j = 0; j < 4; ++j)
#pragma unroll
            for (int c = 0; c < 4; ++c) acc[mt][j][c] = 0.0f;

    gemm_m32n32(acc, hs, ws, row0, nb, g, tg);
    __syncthreads();   // done reading hs/ws; reuse hsf

#pragma unroll
    for (int mt = 0; mt < 2; ++mt)
#pragma unroll
        for (int j = 0; j < 4; ++j) {
            int n0 = nb + j * 8 + 2 * tg;
            float bx = __ldg(&b2[n0]), by = __ldg(&b2[n0 + 1]);
            int r = row0 + mt * 16 + g;
            float h00 = acc[mt][j][0] + bx, h01 = acc[mt][j][1] + by;
            float h10 = acc[mt][j][2] + bx, h11 = acc[mt][j][3] + by;
            float2 v0; v0.x = h00; v0.y = h01;
            float2 v1; v1.x = h10; v1.y = h11;
            *(float2*)&g_h[(size_t)(tok0 + r) * DD + n0]     = v0;
            *(float2*)&g_h[(size_t)(tok0 + r + 8) * DD + n0] = v1;
            hsf[r * 65 + n0] = h00;       hsf[r * 65 + n0 + 1] = h01;
            hsf[(r + 8) * 65 + n0] = h10; hsf[(r + 8) * 65 + n0 + 1] = h11;
        }
    __syncthreads();

    if (t < 128) {
        int tok = tok0 + t;
        float lg0 = gb[0], lg1 = gb[1], lg2 = gb[2], lg3 = gb[3];
#pragma unroll 16
        for (int d = 0; d < 64; ++d) {
            float h = hsf[t * 65 + d];
            const float* g4 = &gws[d * EE];
            lg0 += h * g4[0]; lg1 += h * g4[1]; lg2 += h * g4[2]; lg3 += h * g4[3];
        }
        float m = fmaxf(fmaxf(lg0, lg1), fmaxf(lg2, lg3));
        float e0 = expf(lg0 - m), e1 = expf(lg1 - m);
        float e2 = expf(lg2 - m), e3 = expf(lg3 - m);
        float inv = 1.0f / (e0 + e1 + e2 + e3);
        float p0 = e0 * inv, p1 = e1 * inv, p2 = e2 * inv, p3 = e3 * inv;
        int am = 0; float best = lg0;
        if (lg1 > best) { best = lg1; am = 1; }
        if (lg2 > best) { best = lg2; am = 2; }
        if (lg3 > best) { best = lg3; am = 3; }
        float pe[4] = {p0, p1, p2, p3};
        g_gate[tok] = pe[am];
        int pos = atomicAdd(&g_cnt[am], 1);
        g_idx[(size_t)am * TT + pos] = tok;
        atomicAdd(&sps[0], p0); atomicAdd(&sps[1], p1);
        atomicAdd(&sps[2], p2); atomicAdd(&sps[3], p3);
    }
    __syncthreads();
    if (t < EE) atomicAdd(&g_psum[t], sps[t]);
}

// ------------------- k3: per-expert fused FFN (tf32x3, gathered) -----------
// 64 tokens per block, 128 threads = 4 warps as 2(m) x 2(n), warp m32 x n32
extern __shared__ float2 sm3[];
__global__ void __launch_bounds__(128) k3_expert(const float* __restrict__ ew1,
                                                 const float* __restrict__ eb1,
                                                 const float* __restrict__ ew2,
                                                 const float* __restrict__ eb2) {
    const int e = blockIdx.y;
    const int base = blockIdx.x * 64;
    const int cnt = g_cnt[e];
    if (base >= cnt) return;
    const int n = min(64, cnt - base);

    float2* hs = sm3;                 // [64][64] pitched
    float2* hc = sm3 + 64 * PH2;
    float2* ws = sm3 + 2 * 64 * PH2;
    __shared__ int   stok[64];
    __shared__ float sgate[64];

    const int t = threadIdx.x, lane = t & 31, w = t >> 5;
    const int g = lane >> 2, tg = lane & 3;
    const int row0 = (w & 1) * 32, nb = (w >> 1) * 32;

    if (t < 64) {
        if (t < n) {
            int tok = g_idx[(size_t)e * TT + base + t];
            stok[t] = tok; sgate[t] = g_gate[tok];
        } else { stok[t] = -1; sgate[t] = 0.0f; }
    }
    __syncthreads();

    {   // gather + split h rows
        int row = t >> 1, cb = (t & 1) * 32;
        int tok = stok[row];
        float2* dst = hs + row * PH2 + cb;
        if (tok >= 0) {
            const float* src = g_h + (size_t)tok * DD + cb;
#pragma unroll
            for (int q = 0; q < 8; ++q) {
                float4 v = *(const float4*)(src + q * 4);
                dst[q * 4 + 0] = split_tf(v.x);
                dst[q * 4 + 1] = split_tf(v.y);
                dst[q * 4 + 2] = split_tf(v.z);
                dst[q * 4 + 3] = split_tf(v.w);
            }
        } else {
#pragma unroll
            for (int q = 0; q < 32; ++q) dst[q] = make_float2(0.f, 0.f);
        }
    }

    const float* w1e = ew1 + (size_t)e * DD * HID;
    const float* w2e = ew2 + (size_t)e * HID * DD;
    const float* b1e = eb1 + (size_t)e * HID;
    const float* b2e = eb2 + (size_t)e * DD;

    float acc2[2][4][4];
#pragma unroll
    for (int mt = 0; mt < 2; ++mt)
#pragma unroll
        for (int j = 0; j < 4; ++j)
#pragma unroll
            for (int c = 0; c < 4; ++c) acc2[mt][j][c] = 0.0f;

    for (int ch = 0; ch < HID / 64; ++ch) {
#pragma unroll
        for (int p = 0; p < 32; ++p) {   // stage W1 chunk [64 k][64 n]
            int idx = p * 128 + t;
            int kk = idx >> 6, nn = idx & 63;
            ws[kk * PW2 + nn] = split_tf(w1e[(size_t)kk * HID + ch * 64 + nn]);
        }
        __syncthreads();

        float acc1[2][4][4];
#pragma unroll
        for (int mt = 0; mt < 2; ++mt)
#pragma unroll
            for (int j = 0; j < 4; ++j)
#pragma unroll
                for (int c = 0; c < 4; ++c) acc1[mt][j][c] = 0.0f;

        gemm_m32n32(acc1, hs, ws, row0, nb, g, tg);
        __syncthreads();   // all warps done with W1 & prev-chunk hc

#pragma unroll
        for (int mt = 0; mt < 2; ++mt)
#pragma unroll
            for (int j = 0; j < 4; ++j) {   // gelu -> hc (split)
                int n0 = nb + j * 8 + 2 * tg;
                float bx = __ldg(&b1e[ch * 64 + n0]);
                float by = __ldg(&b1e[ch * 64 + n0 + 1]);
                int r = row0 + mt * 16 + g;
                hc[r * PH2 + n0]           = split_tf(gelu_f(acc1[mt][j][0] + bx));
                hc[r * PH2 + n0 + 1]       = split_tf(gelu_f(acc1[mt][j][1] + by));
                hc[(r + 8) * PH2 + n0]     = split_tf(gelu_f(acc1[mt][j][2] + bx));
                hc[(r + 8) * PH2 + n0 + 1] = split_tf(gelu_f(acc1[mt][j][3] + by));
            }
#pragma unroll
        for (int p = 0; p < 32; ++p) {   // stage W2 chunk [64 j][64 d]
            int idx = p * 128 + t;
            int jj = idx >> 6, nn = idx & 63;
            ws[jj * PW2 + nn] = split_tf(w2e[(size_t)(ch * 64 + jj) * DD + nn]);
        }
        __syncthreads();

        gemm_m32n32(acc2, hc, ws, row0, nb, g, tg);
        __syncthreads();   // before next chunk overwrites ws/hc
    }

    // scatter per-token moe output (scaled by gate) into g_h1 (reused)
#pragma unroll
    for (int mt = 0; mt < 2; ++mt)
#pragma unroll
        for (int j = 0; j < 4; ++j) {
            int n0 = nb + j * 8 + 2 * tg;
            float bx = __ldg(&b2e[n0]), by = __ldg(&b2e[n0 + 1]);
            int r = row0 + mt * 16 + g;
            if (stok[r] >= 0) {
                int tok = stok[r]; float gv = sgate[r];
                float2 v;
                v.x = (acc2[mt][j][0] + bx) * gv;
                v.y = (acc2[mt][j][1] + by) * gv;
                *(float2*)&g_h1[(size_t)tok * DD + n0] = v;
            }
            if (stok[r + 8] >= 0) {
                int tok = stok[r + 8]; float gv = sgate[r + 8];
                float2 v;
                v.x = (acc2[mt][j][2] + bx) * gv;
                v.y = (acc2[mt][j][3] + by) * gv;
                *(float2*)&g_h1[(size_t)tok * DD + n0] = v;
            }
        }
}

// ------------------- k3b: deterministic mean over S ------------------------
__global__ void __launch_bounds__(256) k3b_reduce() {
    __shared__ float red[4][64];
    int b = blockIdx.x, t = threadIdx.x;
    int d = t & 63, grp = t >> 6;
    const float* src = g_h1 + (size_t)b * SS * DD;
    float s = 0.0f;
    for (int i = grp * 256; i < grp * 256 + 256; ++i)
        s += src[(size_t)i * DD + d];
    red[grp][d] = s;
    __syncthreads();
    if (t < 64)
        g_z[b * DD + t] = (red[0][t] + red[1][t] + red[2][t] + red[3][t]) * (1.0f / (float)SS);
}

// ------------------- k4: LayerNorm + classifier + aux loss -----------------
__global__ void k4_cls(const float* __restrict__ lng, const float* __restrict__ lnb,
                       const float* __restrict__ w1,  const float* __restrict__ b1,
                       const float* __restrict__ w2,  const float* __restrict__ b2,
                       float* __restrict__ out, int out_size) {
    int b = threadIdx.x;   // 128
    float zr[DD];
    float s = 0.0f;
#pragma unroll
    for (int d = 0; d < DD; ++d) { float v = g_z[b * DD + d]; zr[d] = v; s += v; }
    float mu = s * (1.0f / DD);
    float ss2 = 0.0f;
#pragma unroll
    for (int d = 0; d < DD; ++d) { float c = zr[d] - mu; ss2 += c * c; }
    float inv = rsqrtf(ss2 * (1.0f / DD) + 1e-5f);
#pragma unroll
    for (int d = 0; d < DD; ++d)
        zr[d] = (zr[d] - mu) * inv * lng[d] + lnb[d];

    float h[DD];
#pragma unroll
    for (int o = 0; o < DD; ++o) h[o] = b1[o];
    for (int d = 0; d < DD; ++d) {
        float zd = zr[d];
#pragma unroll
        for (int o = 0; o < DD; ++o) h[o] += zd * w1[d * DD + o];
    }
#pragma unroll
    for (int o = 0; o < DD; ++o) h[o] = gelu_f(h[o]);

    float y[NCLS];
#pragma unroll
    for (int c = 0; c < NCLS; ++c) y[c] = b2[c];
    for (int o = 0; o < DD; ++o) {
        float ho = h[o];
#pragma unroll
        for (int c = 0; c < NCLS; ++c) y[c] += ho * w2[o * NCLS + c];
    }
#pragma unroll
    for (int c = 0; c < NCLS; ++c) out[b * NCLS + c] = y[c];

    if (b == 0) {
        float aux = 0.0f;
        for (int e = 0; e < EE; ++e) {
            float f = (float)g_cnt[e] / (float)TT;
            float p = g_psum[e] / (float)TT;
            aux += f * p;
        }
        out[out_size - 1] = (float)EE * aux;
    }
}

// ----------------------------- launch ---------------------------------------
extern "C" void kernel_launch(void* const* d_in, const int* in_sizes, int n_in,
                              void* d_out, int out_size) {
    const float* x      = (const float*)d_in[0];
    const float* pe_w1  = (const float*)d_in[1];
    const float* pe_b1  = (const float*)d_in[2];
    const float* pe_w2  = (const float*)d_in[3];
    const float* pe_b2  = (const float*)d_in[4];
    const float* gate_w = (const float*)d_in[5];
    const float* gate_b = (const float*)d_in[6];
    const float* ew1    = (const float*)d_in[7];
    const float* eb1    = (const float*)d_in[8];
    const float* ew2    = (const float*)d_in[9];
    const float* eb2    = (const float*)d_in[10];
    const float* ln_g   = (const float*)d_in[11];
    const float* ln_b   = (const float*)d_in[12];
    const float* cl_w1  = (const float*)d_in[13];
    const float* cl_b1  = (const float*)d_in[14];
    const float* cl_w2  = (const float*)d_in[15];
    const float* cl_b2  = (const float*)d_in[16];

    const int smem12 = (128 * PH2 + 64 * PW2) * 8;   // 101376 B
    const int smem3  = (3 * 64 * PH2) * 8;           // 101376 B
    cudaFuncSetAttribute(k1_pe1,      cudaFuncAttributeMaxDynamicSharedMemorySize, smem12);
    cudaFuncSetAttribute(k2_pe2_gate, cudaFuncAttributeMaxDynamicSharedMemorySize, smem12);
    cudaFuncSetAttribute(k3_expert,   cudaFuncAttributeMaxDynamicSharedMemorySize, smem3);

    k0_zero<<<1, 32>>>();
    k1_pe1<<<TT / 128, 256, smem12>>>(x, pe_w1, pe_b1);
    k2_pe2_gate<<<TT / 128, 256, smem12>>>(pe_w2, pe_b2, gate_w, gate_b);
    k3_expert<<<dim3(TT / 64, EE), 128, smem3>>>(ew1, eb1, ew2, eb2);
    k3b_reduce<<<BB, 256>>>();
    k4_cls<<<1, 128>>>(ln_g, ln_b, cl_w1, cl_b1, cl_w2, cl_b2,
                       (float*)d_out, out_size);
}

// round 7
// speedup vs baseline: 1.0352x; 1.0352x over previous
#include <cuda_runtime.h>
#include <math.h>

#define BB   128
#define SS   1024
#define TT   (BB*SS)          // 131072 tokens
#define IND  192
#define DD   64
#define EE   4
#define HID  256
#define NCLS 10

#define PH2 66   // activation tile pitch in float2
#define PW2 66   // weight tile pitch in float2
#define CHF2 (64 * PW2)          // float2 per weight chunk (4224)
#define CHB  (CHF2 * 8)          // bytes per chunk (33792)
#define NCPA (CHB / 16)          // 16B cp.async ops per chunk (2112)

// ------------------------- scratch (device globals) ------------------------
__device__ float g_h1[(size_t)TT * DD];      // h1; later reused as moe output
__device__ float g_h [(size_t)TT * DD];      // h = h1@W2+b2
__device__ float g_gate[TT];
__device__ int   g_idx[(size_t)EE * TT];
__device__ int   g_cnt[EE];
__device__ float g_psum[EE];
__device__ float g_z[BB * DD];
// pre-split weights: 36 chunks, each the exact smem image ([k][n] hi/lo, pitched)
// cid 0..2: pe_w1 (it) | 3: pe_w2 | 4+e*4+ch: expert W1 | 20+e*4+ch: expert W2
__device__ __align__(16) float2 g_wsp[(size_t)36 * CHF2];

__device__ __forceinline__ float gelu_f(float v) {
    return 0.5f * v * (1.0f + erff(v * 0.70710678118654752440f));
}
// split fp32 into tf32 hi + tf32 lo
__device__ __forceinline__ float2 split_tf(float f) {
    unsigned hu, lu;
    asm("cvt.rna.tf32.f32 %0, %1;" : "=r"(hu) : "f"(f));
    float hi = __uint_as_float(hu);
    asm("cvt.rna.tf32.f32 %0, %1;" : "=r"(lu) : "f"(f - hi));
    return make_float2(hi, __uint_as_float(lu));
}
__device__ __forceinline__ unsigned su32(const void* p) {
    return (unsigned)__cvta_generic_to_shared(p);
}
__device__ __forceinline__ void cpa16(unsigned dst, const void* src) {
    asm volatile("cp.async.cg.shared.global [%0], [%1], 16;" :: "r"(dst), "l"(src));
}
#define CPA_COMMIT() asm volatile("cp.async.commit_group;" ::: "memory")
#define CPA_WAIT0()  asm volatile("cp.async.wait_group 0;" ::: "memory")
#define CPA_WAIT1()  asm volatile("cp.async.wait_group 1;" ::: "memory")

// copy one pre-split weight chunk into smem (256 threads)
__device__ __forceinline__ void stage_ws_async(float2* dst, const float2* src, int t) {
    unsigned d = su32(dst);
    const char* s = (const char*)src;
    for (int i = t; i < NCPA; i += 256)
        cpa16(d + i * 16, s + i * 16);
}

__device__ __forceinline__ void mma8(float* c, const unsigned* a, unsigned b0, unsigned b1) {
    asm volatile(
        "mma.sync.aligned.m16n8k8.row.col.f32.tf32.tf32.f32 "
        "{%0,%1,%2,%3},{%4,%5,%6,%7},{%8,%9},{%0,%1,%2,%3};"
        : "+f"(c[0]), "+f"(c[1]), "+f"(c[2]), "+f"(c[3])
        : "r"(a[0]), "r"(a[1]), "r"(a[2]), "r"(a[3]), "r"(b0), "r"(b1));
}
// tf32x3: acc += al*bh + ah*bl + ah*bh
__device__ __forceinline__ void mma3(float* c, const unsigned* ah, const unsigned* al,
                                     unsigned bh0, unsigned bh1, unsigned bl0, unsigned bl1) {
    mma8(c, al, bh0, bh1);
    mma8(c, ah, bl0, bl1);
    mma8(c, ah, bh0, bh1);
}
__device__ __forceinline__ void ldA2(unsigned* ah, unsigned* al,
                                     const float2* base, int pitch, int g, int tg) {
    float2 v0 = base[g * pitch + tg];
    float2 v1 = base[(g + 8) * pitch + tg];
    float2 v2 = base[g * pitch + tg + 4];
    float2 v3 = base[(g + 8) * pitch + tg + 4];
    ah[0] = __float_as_uint(v0.x); al[0] = __float_as_uint(v0.y);
    ah[1] = __float_as_uint(v1.x); al[1] = __float_as_uint(v1.y);
    ah[2] = __float_as_uint(v2.x); al[2] = __float_as_uint(v2.y);
    ah[3] = __float_as_uint(v3.x); al[3] = __float_as_uint(v3.y);
}
// one warp's m32 x n32 x k64 tf32x3 GEMM over pitched float2 tiles
__device__ __forceinline__ void gemm_m32n32(float acc[2][4][4],
                                            const float2* A, const float2* W,
                                            int row0, int nb, int g, int tg) {
#pragma unroll
    for (int ks = 0; ks < 64; ks += 8) {
        unsigned ah0[4], al0[4], ah1[4], al1[4];
        ldA2(ah0, al0, A + row0 * PH2 + ks, PH2, g, tg);
        ldA2(ah1, al1, A + (row0 + 16) * PH2 + ks, PH2, g, tg);
#pragma unroll
        for (int j = 0; j < 4; ++j) {
            float2 wb0 = W[(ks + tg) * PW2 + nb + j * 8 + g];
            float2 wb1 = W[(ks + tg + 4) * PW2 + nb + j * 8 + g];
            unsigned bh0 = __float_as_uint(wb0.x), bh1 = __float_as_uint(wb1.x);
            unsigned bl0 = __float_as_uint(wb0.y), bl1 = __float_as_uint(wb1.y);
            mma3(acc[0][j], ah0, al0, bh0, bh1, bl0, bl1);
            mma3(acc[1][j], ah1, al1, bh0, bh1, bl0, bl1);
        }
    }
}

// ------------------------- k_pre: split+layout all weights ------------------
// smem image layout is W[k * PW2 + n]  (row = k, col = n) — matches gemm_m32n32
__global__ void __launch_bounds__(256) k_pre(const float* __restrict__ pw1,
                                             const float* __restrict__ pw2,
                                             const float* __restrict__ ew1,
                                             const float* __restrict__ ew2) {
    const int cid = blockIdx.x, t = threadIdx.x;
    float2* dst = g_wsp + (size_t)cid * CHF2;
#pragma unroll
    for (int p = 0; p < 16; ++p) {
        int idx = p * 256 + t;
        int n = idx >> 6, k = idx & 63;
        float v;
        if (cid < 3)        v = pw1[(size_t)(cid * 64 + k) * DD + n];
        else if (cid == 3)  v = pw2[(size_t)k * DD + n];
        else if (cid < 20) {
            int e = (cid - 4) >> 2, ch = (cid - 4) & 3;
            v = ew1[(size_t)e * DD * HID + (size_t)k * HID + ch * 64 + n];
        } else {
            int e = (cid - 20) >> 2, ch = (cid - 20) & 3;
            v = ew2[(size_t)e * HID * DD + (size_t)(ch * 64 + k) * DD + n];
        }
        dst[k * PW2 + n] = split_tf(v);
    }
}

// ------------------------- k0: zero counters -------------------------------
__global__ void k0_zero() {
    int t = threadIdx.x;
    if (t < EE) { g_cnt[t] = 0; g_psum[t] = 0.0f; }
}

// ------------------------- k1: h1 = gelu(x @ W1 + b1) ----------------------
extern __shared__ float2 sm1[];
__global__ void __launch_bounds__(256) k1_pe1(const float* __restrict__ x,
                                              const float* __restrict__ b1) {
    float2* xs = sm1;                 // [128][64] pitched PH2
    float2* ws = sm1 + 128 * PH2;

    const int t = threadIdx.x, lane = t & 31, w = t >> 5;
    const int g = lane >> 2, tg = lane & 3;
    const int row0 = (w & 3) * 32, nb = (w >> 2) * 32;
    const int tok0 = blockIdx.x * 128;

    float acc[2][4][4];
#pragma unroll
    for (int mt = 0; mt < 2; ++mt)
#pragma unroll
        for (int j = 0; j < 4; ++j)
#pragma unroll
            for (int c = 0; c < 4; ++c) acc[mt][j][c] = 0.0f;

    for (int it = 0; it < 3; ++it) {
        if (it) __syncthreads();
        stage_ws_async(ws, g_wsp + (size_t)it * CHF2, t);
        CPA_COMMIT();
        {   // stage x chunk [128][64] split (overlaps with cp.async)
            int row = t >> 1, cb = (t & 1) * 32;
            const float* src = x + (size_t)(tok0 + row) * IND + it * 64 + cb;
            float2* dst = xs + row * PH2 + cb;
#pragma unroll
            for (int q = 0; q < 8; ++q) {
                float4 v = *(const float4*)(src + q * 4);
                dst[q * 4 + 0] = split_tf(v.x);
                dst[q * 4 + 1] = split_tf(v.y);
                dst[q * 4 + 2] = split_tf(v.z);
                dst[q * 4 + 3] = split_tf(v.w);
            }
        }
        CPA_WAIT0();
        __syncthreads();
        gemm_m32n32(acc, xs, ws, row0, nb, g, tg);
    }

#pragma unroll
    for (int mt = 0; mt < 2; ++mt)
#pragma unroll
        for (int j = 0; j < 4; ++j) {
            int n0 = nb + j * 8 + 2 * tg;
            float bx = __ldg(&b1[n0]), by = __ldg(&b1[n0 + 1]);
            int r = tok0 + row0 + mt * 16 + g;
            float2 v0, v1;
            v0.x = gelu_f(acc[mt][j][0] + bx); v0.y = gelu_f(acc[mt][j][1] + by);
            v1.x = gelu_f(acc[mt][j][2] + bx); v1.y = gelu_f(acc[mt][j][3] + by);
            *(float2*)&g_h1[(size_t)r * DD + n0]       = v0;
            *(float2*)&g_h1[(size_t)(r + 8) * DD + n0] = v1;
        }
}

// ------------------- k2: h = h1 @ W2 + b2, fused gate ----------------------
extern __shared__ float2 sm2[];
__global__ void __launch_bounds__(256) k2_pe2_gate(const float* __restrict__ b2,
                                                   const float* __restrict__ gw,
                                                   const float* __restrict__ gb) {
    float2* hs = sm2;
    float2* ws = sm2 + 128 * PH2;
    float*  hsf = (float*)sm2;        // alias after GEMM: [128][65] fp32
    __shared__ float gws[DD * EE];
    __shared__ float sps[EE];

    const int t = threadIdx.x, lane = t & 31, w = t >> 5;
    const int g = lane >> 2, tg = lane & 3;
    const int row0 = (w & 3) * 32, nb = (w >> 2) * 32;
    const int tok0 = blockIdx.x * 128;

    stage_ws_async(ws, g_wsp + (size_t)3 * CHF2, t);
    CPA_COMMIT();

    gws[t] = gw[t];                   // 256 == DD*EE
    if (t < EE) sps[t] = 0.0f;

    {   // stage h1 tile [128][64]
        int row = t >> 1, cb = (t & 1) * 32;
        const float* src = g_h1 + (size_t)(tok0 + row) * DD + cb;
        float2* dst = hs + row * PH2 + cb;
#pragma unroll
        for (int q = 0; q < 8; ++q) {
            float4 v = *(const float4*)(src + q * 4);
            dst[q * 4 + 0] = split_tf(v.x);
            dst[q * 4 + 1] = split_tf(v.y);
            dst[q * 4 + 2] = split_tf(v.z);
            dst[q * 4 + 3] = split_tf(v.w);
        }
    }
    CPA_WAIT0();
    __syncthreads();

    float acc[2][4][4];
#pragma unroll
    for (int mt = 0; mt < 2; ++mt)
#pragma unroll
        for (int j = 0; j < 4; ++j)
#pragma unroll
            for (int c = 0; c < 4; ++c) acc[mt][j][c] = 0.0f;

    gemm_m32n32(acc, hs, ws, row0, nb, g, tg);
    __syncthreads();   // done reading hs/ws; reuse hsf

#pragma unroll
    for (int mt = 0; mt < 2; ++mt)
#pragma unroll
        for (int j = 0; j < 4; ++j) {
            int n0 = nb + j * 8 + 2 * tg;
            float bx = __ldg(&b2[n0]), by = __ldg(&b2[n0 + 1]);
            int r = row0 + mt * 16 + g;
            float h00 = acc[mt][j][0] + bx, h01 = acc[mt][j][1] + by;
            float h10 = acc[mt][j][2] + bx, h11 = acc[mt][j][3] + by;
            float2 v0; v0.x = h00; v0.y = h01;
            float2 v1; v1.x = h10; v1.y = h11;
            *(float2*)&g_h[(size_t)(tok0 + r) * DD + n0]     = v0;
            *(float2*)&g_h[(size_t)(tok0 + r + 8) * DD + n0] = v1;
            hsf[r * 65 + n0] = h00;       hsf[r * 65 + n0 + 1] = h01;
            hsf[(r + 8) * 65 + n0] = h10; hsf[(r + 8) * 65 + n0 + 1] = h11;
        }
    __syncthreads();

    if (t < 128) {
        int tok = tok0 + t;
        float lg0 = gb[0], lg1 = gb[1], lg2 = gb[2], lg3 = gb[3];
#pragma unroll 16
        for (int d = 0; d < 64; ++d) {
            float h = hsf[t * 65 + d];
            const float* g4 = &gws[d * EE];
            lg0 += h * g4[0]; lg1 += h * g4[1]; lg2 += h * g4[2]; lg3 += h * g4[3];
        }
        float m = fmaxf(fmaxf(lg0, lg1), fmaxf(lg2, lg3));
        float e0 = expf(lg0 - m), e1 = expf(lg1 - m);
        float e2 = expf(lg2 - m), e3 = expf(lg3 - m);
        float inv = 1.0f / (e0 + e1 + e2 + e3);
        float p0 = e0 * inv, p1 = e1 * inv, p2 = e2 * inv, p3 = e3 * inv;
        int am = 0; float best = lg0;
        if (lg1 > best) { best = lg1; am = 1; }
        if (lg2 > best) { best = lg2; am = 2; }
        if (lg3 > best) { best = lg3; am = 3; }
        float pe[4] = {p0, p1, p2, p3};
        g_gate[tok] = pe[am];
        int pos = atomicAdd(&g_cnt[am], 1);
        g_idx[(size_t)am * TT + pos] = tok;
        atomicAdd(&sps[0], p0); atomicAdd(&sps[1], p1);
        atomicAdd(&sps[2], p2); atomicAdd(&sps[3], p3);
    }
    __syncthreads();
    if (t < EE) atomicAdd(&g_psum[t], sps[t]);
}

// ------------------- k3: per-expert fused FFN (double-buffered cp.async) ---
// 128 tokens/block, 256 threads = 8 warps as 4(m) x 2(n), warp m32 x n32
extern __shared__ float2 sm3[];
__global__ void __launch_bounds__(256) k3_expert(const float* __restrict__ eb1,
                                                 const float* __restrict__ eb2) {
    const int e = blockIdx.y;
    const int base = blockIdx.x * 128;
    const int cnt = g_cnt[e];
    if (base >= cnt) return;
    const int n = min(128, cnt - base);

    float2* hs  = sm3;                        // [128][64] pitched
    float2* hc  = sm3 + 128 * PH2;
    float2* ws0 = sm3 + 2 * 128 * PH2;        // W1 buffer
    float2* ws1 = ws0 + CHF2;                 // W2 buffer
    __shared__ int   stok[128];
    __shared__ float sgate[128];

    const int t = threadIdx.x, lane = t & 31, w = t >> 5;
    const int g = lane >> 2, tg = lane & 3;
    const int row0 = (w & 3) * 32, nb = (w >> 2) * 32;

    const float2* W1base = g_wsp + (size_t)(4 + e * 4) * CHF2;
    const float2* W2base = g_wsp + (size_t)(20 + e * 4) * CHF2;
    const float* b1e = eb1 + (size_t)e * HID;
    const float* b2e = eb2 + (size_t)e * DD;

    // prefetch W1 chunk 0 immediately
    stage_ws_async(ws0, W1base, t);
    CPA_COMMIT();

    if (t < 128) {
        if (t < n) {
            int tok = g_idx[(size_t)e * TT + base + t];
            stok[t] = tok; sgate[t] = g_gate[tok];
        } else { stok[t] = -1; sgate[t] = 0.0f; }
    }
    __syncthreads();

    {   // gather + split h rows (overlaps with W1c0 cp.async)
        int row = t >> 1, cb = (t & 1) * 32;
        int tok = stok[row];
        float2* dst = hs + row * PH2 + cb;
        if (tok >= 0) {
            const float* src = g_h + (size_t)tok * DD + cb;
#pragma unroll
            for (int q = 0; q < 8; ++q) {
                float4 v = *(const float4*)(src + q * 4);
                dst[q * 4 + 0] = split_tf(v.x);
                dst[q * 4 + 1] = split_tf(v.y);
                dst[q * 4 + 2] = split_tf(v.z);
                dst[q * 4 + 3] = split_tf(v.w);
            }
        } else {
#pragma unroll
            for (int q = 0; q < 32; ++q) dst[q] = make_float2(0.f, 0.f);
        }
    }

    float acc2[2][4][4];
#pragma unroll
    for (int mt = 0; mt < 2; ++mt)
#pragma unroll
        for (int j = 0; j < 4; ++j)
#pragma unroll
            for (int c = 0; c < 4; ++c) acc2[mt][j][c] = 0.0f;

    for (int ch = 0; ch < HID / 64; ++ch) {
        if (ch) __syncthreads();   // prev GEMM2 done with ws1/hc

        // prefetch W2(ch) into ws1; runs under GEMM1
        stage_ws_async(ws1, W2base + (size_t)ch * CHF2, t);
        CPA_COMMIT();

        CPA_WAIT1();               // W1(ch) landed
        __syncthreads();           // + hs/gather visible (ch==0)

        float acc1[2][4][4];
#pragma unroll
        for (int mt = 0; mt < 2; ++mt)
#pragma unroll
            for (int j = 0; j < 4; ++j)
#pragma unroll
                for (int c = 0; c < 4; ++c) acc1[mt][j][c] = 0.0f;

        gemm_m32n32(acc1, hs, ws0, row0, nb, g, tg);

#pragma unroll
        for (int mt = 0; mt < 2; ++mt)
#pragma unroll
            for (int j = 0; j < 4; ++j) {   // gelu -> hc (split)
                int n0 = nb + j * 8 + 2 * tg;
                float bx = __ldg(&b1e[ch * 64 + n0]);
                float by = __ldg(&b1e[ch * 64 + n0 + 1]);
                int r = row0 + mt * 16 + g;
                hc[r * PH2 + n0]           = split_tf(gelu_f(acc1[mt][j][0] + bx));
                hc[r * PH2 + n0 + 1]       = split_tf(gelu_f(acc1[mt][j][1] + by));
                hc[(r + 8) * PH2 + n0]     = split_tf(gelu_f(acc1[mt][j][2] + bx));
                hc[(r + 8) * PH2 + n0 + 1] = split_tf(gelu_f(acc1[mt][j][3] + by));
            }
        __syncthreads();           // ws0 free, hc ready

        if (ch < HID / 64 - 1) {   // prefetch W1(ch+1) into ws0; runs under GEMM2
            stage_ws_async(ws0, W1base + (size_t)(ch + 1) * CHF2, t);
            CPA_COMMIT();
            CPA_WAIT1();           // W2(ch) landed
        } else {
            CPA_WAIT0();
        }
        __syncthreads();

        gemm_m32n32(acc2, hc, ws1, row0, nb, g, tg);
    }

    // scatter per-token moe output (scaled by gate) into g_h1 (reused)
#pragma unroll
    for (int mt = 0; mt < 2; ++mt)
#pragma unroll
        for (int j = 0; j < 4; ++j) {
            int n0 = nb + j * 8 + 2 * tg;
            float bx = __ldg(&b2e[n0]), by = __ldg(&b2e[n0 + 1]);
            int r = row0 + mt * 16 + g;
            if (stok[r] >= 0) {
                int tok = stok[r]; float gv = sgate[r];
                float2 v;
                v.x = (acc2[mt][j][0] + bx) * gv;
                v.y = (acc2[mt][j][1] + by) * gv;
                *(float2*)&g_h1[(size_t)tok * DD + n0] = v;
            }
            if (stok[r + 8] >= 0) {
                int tok = stok[r + 8]; float gv = sgate[r + 8];
                float2 v;
                v.x = (acc2[mt][j][2] + bx) * gv;
                v.y = (acc2[mt][j][3] + by) * gv;
                *(float2*)&g_h1[(size_t)tok * DD + n0] = v;
            }
        }
}

// ------------------- k3b: deterministic mean over S ------------------------
__global__ void __launch_bounds__(256) k3b_reduce() {
    __shared__ float red[4][64];
    int b = blockIdx.x, t = threadIdx.x;
    int d = t & 63, grp = t >> 6;
    const float* src = g_h1 + (size_t)b * SS * DD;
    float s = 0.0f;
    for (int i = grp * 256; i < grp * 256 + 256; ++i)
        s += src[(size_t)i * DD + d];
    red[grp][d] = s;
    __syncthreads();
    if (t < 64)
        g_z[b * DD + t] = (red[0][t] + red[1][t] + red[2][t] + red[3][t]) * (1.0f / (float)SS);
}

// ------------------- k4: LayerNorm + classifier + aux loss -----------------
__global__ void k4_cls(const float* __restrict__ lng, const float* __restrict__ lnb,
                       const float* __restrict__ w1,  const float* __restrict__ b1,
                       const float* __restrict__ w2,  const float* __restrict__ b2,
                       float* __restrict__ out, int out_size) {
    int b = threadIdx.x;   // 128
    float zr[DD];
    float s = 0.0f;
#pragma unroll
    for (int d = 0; d < DD; ++d) { float v = g_z[b * DD + d]; zr[d] = v; s += v; }
    float mu = s * (1.0f / DD);
    float ss2 = 0.0f;
#pragma unroll
    for (int d = 0; d < DD; ++d) { float c = zr[d] - mu; ss2 += c * c; }
    float inv = rsqrtf(ss2 * (1.0f / DD) + 1e-5f);
#pragma unroll
    for (int d = 0; d < DD; ++d)
        zr[d] = (zr[d] - mu) * inv * lng[d] + lnb[d];

    float h[DD];
#pragma unroll
    for (int o = 0; o < DD; ++o) h[o] = b1[o];
    for (int d = 0; d < DD; ++d) {
        float zd = zr[d];
#pragma unroll
        for (int o = 0; o < DD; ++o) h[o] += zd * w1[d * DD + o];
    }
#pragma unroll
    for (int o = 0; o < DD; ++o) h[o] = gelu_f(h[o]);

    float y[NCLS];
#pragma unroll
    for (int c = 0; c < NCLS; ++c) y[c] = b2[c];
    for (int o = 0; o < DD; ++o) {
        float ho = h[o];
#pragma unroll
        for (int c = 0; c < NCLS; ++c) y[c] += ho * w2[o * NCLS + c];
    }
#pragma unroll
    for (int c = 0; c < NCLS; ++c) out[b * NCLS + c] = y[c];

    if (b == 0) {
        float aux = 0.0f;
        for (int e = 0; e < EE; ++e) {
            float f = (float)g_cnt[e] / (float)TT;
            float p = g_psum[e] / (float)TT;
            aux += f * p;
        }
        out[out_size - 1] = (float)EE * aux;
    }
}

// ----------------------------- launch ---------------------------------------
extern "C" void kernel_launch(void* const* d_in, const int* in_sizes, int n_in,
                              void* d_out, int out_size) {
    const float* x      = (const float*)d_in[0];
    const float* pe_w1  = (const float*)d_in[1];
    const float* pe_b1  = (const float*)d_in[2];
    const float* pe_w2  = (const float*)d_in[3];
    const float* pe_b2  = (const float*)d_in[4];
    const float* gate_w = (const float*)d_in[5];
    const float* gate_b = (const float*)d_in[6];
    const float* ew1    = (const float*)d_in[7];
    const float* eb1    = (const float*)d_in[8];
    const float* ew2    = (const float*)d_in[9];
    const float* eb2    = (const float*)d_in[10];
    const float* ln_g   = (const float*)d_in[11];
    const float* ln_b   = (const float*)d_in[12];
    const float* cl_w1  = (const float*)d_in[13];
    const float* cl_b1  = (const float*)d_in[14];
    const float* cl_w2  = (const float*)d_in[15];
    const float* cl_b2  = (const float*)d_in[16];

    const int smem12 = (128 * PH2 + CHF2) * 8;        // 101376 B
    const int smem3  = (2 * 128 * PH2 + 2 * CHF2) * 8; // 202752 B
    cudaFuncSetAttribute(k1_pe1,      cudaFuncAttributeMaxDynamicSharedMemorySize, smem12);
    cudaFuncSetAttribute(k2_pe2_gate, cudaFuncAttributeMaxDynamicSharedMemorySize, smem12);
    cudaFuncSetAttribute(k3_expert,   cudaFuncAttributeMaxDynamicSharedMemorySize, smem3);

    k_pre<<<36, 256>>>(pe_w1, pe_w2, ew1, ew2);
    k0_zero<<<1, 32>>>();
    k1_pe1<<<TT / 128, 256, smem12>>>(x, pe_b1);
    k2_pe2_gate<<<TT / 128, 256, smem12>>>(pe_b2, gate_w, gate_b);
    k3_expert<<<dim3(TT / 128, EE), 256, smem3>>>(eb1, eb2);
    k3b_reduce<<<BB, 256>>>();
    k4_cls<<<1, 128>>>(ln_g, ln_b, cl_w1, cl_b1, cl_w2, cl_b2,
                       (float*)d_out, out_size);
}